// round 1
// baseline (speedup 1.0000x reference)
#include <cuda_runtime.h>
#include <math.h>

// Causal memory-efficient attention, fp32, B=4 H=16 S=4096 D=64.
// One CTA per (bh, 64-row q-tile). Flash-attention mainloop over 64-row k/v tiles.
// 256 threads, each owning a 4x4 output micro-tile (rows = q, cols = d).

#define BM 64      // q rows per CTA
#define BN 64      // k rows per tile
#define DHEAD 64
#define PITCH 68   // smem row pitch in floats (68*4 bytes, 16B aligned, conflict-free)
#define NTHREADS 256
#define SEQ 4096
#define NBH 64     // B*H

__global__ void __launch_bounds__(NTHREADS)
mea_fp32_kernel(const float* __restrict__ Q, const float* __restrict__ K,
                const float* __restrict__ V, float* __restrict__ O) {
    extern __shared__ float smem[];
    float* Qs   = smem;                 // [BM][PITCH]
    float* Ks   = Qs + BM * PITCH;      // [BN][PITCH]
    float* Vs   = Ks + BN * PITCH;      // [BN][PITCH]
    float* Ss   = Vs + BN * PITCH;      // [BM][PITCH]  (scores, then probabilities)
    float* mrow = Ss + BM * PITCH;      // [BM] running max
    float* lrow = mrow + BM;            // [BM] running denom
    float* arow = lrow + BM;            // [BM] rescale factor per tile

    const int qt  = blockIdx.x;         // q tile index
    const int bh  = blockIdx.y;         // batch*head
    const int tid = threadIdx.x;
    const size_t base = (size_t)bh * SEQ * DHEAD;
    const float scale = 0.125f;         // 1/sqrt(64)

    // ---- Load Q tile (pre-scaled) ----
    #pragma unroll
    for (int t = tid; t < BM * 16; t += NTHREADS) {
        int row = t >> 4;
        int c4  = (t & 15) << 2;
        float4 v = *(const float4*)(Q + base + (size_t)(qt * BM + row) * DHEAD + c4);
        v.x *= scale; v.y *= scale; v.z *= scale; v.w *= scale;
        *(float4*)(Qs + row * PITCH + c4) = v;
    }
    if (tid < BM) { mrow[tid] = -INFINITY; lrow[tid] = 0.0f; }

    float acc[4][4];
    #pragma unroll
    for (int r = 0; r < 4; r++)
        #pragma unroll
        for (int c = 0; c < 4; c++) acc[r][c] = 0.0f;

    const int ty = tid >> 4;   // 0..15, q-row group (rows ty*4 .. ty*4+3)
    const int tx = tid & 15;   // 0..15, d-col group (cols tx*4 .. tx*4+3)

    __syncthreads();

    for (int kt = 0; kt <= qt; kt++) {
        // ---- Load K, V tiles ----
        #pragma unroll
        for (int t = tid; t < BN * 16; t += NTHREADS) {
            int row = t >> 4;
            int c4  = (t & 15) << 2;
            size_t g = base + (size_t)(kt * BN + row) * DHEAD + c4;
            *(float4*)(Ks + row * PITCH + c4) = *(const float4*)(K + g);
            *(float4*)(Vs + row * PITCH + c4) = *(const float4*)(V + g);
        }
        __syncthreads();

        // ---- S = Q * K^T (each thread: 4 q-rows x 4 k-cols) ----
        float s[4][4];
        #pragma unroll
        for (int r = 0; r < 4; r++)
            #pragma unroll
            for (int c = 0; c < 4; c++) s[r][c] = 0.0f;

        #pragma unroll 4
        for (int d = 0; d < DHEAD; d += 4) {
            float4 b0 = *(const float4*)(Ks + (tx * 4 + 0) * PITCH + d);
            float4 b1 = *(const float4*)(Ks + (tx * 4 + 1) * PITCH + d);
            float4 b2 = *(const float4*)(Ks + (tx * 4 + 2) * PITCH + d);
            float4 b3 = *(const float4*)(Ks + (tx * 4 + 3) * PITCH + d);
            #pragma unroll
            for (int r = 0; r < 4; r++) {
                float4 a = *(const float4*)(Qs + (ty * 4 + r) * PITCH + d);
                s[r][0] += a.x * b0.x + a.y * b0.y + a.z * b0.z + a.w * b0.w;
                s[r][1] += a.x * b1.x + a.y * b1.y + a.z * b1.z + a.w * b1.w;
                s[r][2] += a.x * b2.x + a.y * b2.y + a.z * b2.z + a.w * b2.w;
                s[r][3] += a.x * b3.x + a.y * b3.y + a.z * b3.z + a.w * b3.w;
            }
        }
        // Stash scores to smem
        #pragma unroll
        for (int r = 0; r < 4; r++) {
            float4 sv = make_float4(s[r][0], s[r][1], s[r][2], s[r][3]);
            *(float4*)(Ss + (ty * 4 + r) * PITCH + tx * 4) = sv;
        }
        __syncthreads();

        // ---- Online softmax: 4 threads per row, 16 cols each ----
        {
            const int  row   = tid >> 2;        // 0..63
            const int  p     = tid & 3;         // 0..3
            const bool diag  = (kt == qt);
            const int  qglob = qt * BM + row;

            float vals[16];
            float mloc = -INFINITY;
            #pragma unroll
            for (int jj = 0; jj < 16; jj++) {
                int j = p * 16 + jj;
                float v = Ss[row * PITCH + j];
                if (diag && (kt * BN + j) > qglob) v = -INFINITY;
                vals[jj] = v;
                mloc = fmaxf(mloc, v);
            }
            mloc = fmaxf(mloc, __shfl_xor_sync(0xffffffffu, mloc, 1));
            mloc = fmaxf(mloc, __shfl_xor_sync(0xffffffffu, mloc, 2));

            float mold = mrow[row];
            float mnew = fmaxf(mold, mloc);

            float sum = 0.0f;
            #pragma unroll
            for (int jj = 0; jj < 16; jj++) {
                float e = __expf(vals[jj] - mnew);
                Ss[row * PITCH + p * 16 + jj] = e;
                sum += e;
            }
            sum += __shfl_xor_sync(0xffffffffu, sum, 1);
            sum += __shfl_xor_sync(0xffffffffu, sum, 2);

            __syncwarp();   // order reads of mrow/lrow before p==0 writes
            if (p == 0) {
                float al = __expf(mold - mnew);
                arow[row] = al;
                lrow[row] = lrow[row] * al + sum;
                mrow[row] = mnew;
            }
        }
        __syncthreads();

        // ---- Rescale accumulators ----
        #pragma unroll
        for (int r = 0; r < 4; r++) {
            float al = arow[ty * 4 + r];
            #pragma unroll
            for (int c = 0; c < 4; c++) acc[r][c] *= al;
        }

        // ---- O += P * V ----
        #pragma unroll 4
        for (int j = 0; j < BN; j += 4) {
            float4 v0 = *(const float4*)(Vs + (j + 0) * PITCH + tx * 4);
            float4 v1 = *(const float4*)(Vs + (j + 1) * PITCH + tx * 4);
            float4 v2 = *(const float4*)(Vs + (j + 2) * PITCH + tx * 4);
            float4 v3 = *(const float4*)(Vs + (j + 3) * PITCH + tx * 4);
            #pragma unroll
            for (int r = 0; r < 4; r++) {
                float4 pv = *(const float4*)(Ss + (ty * 4 + r) * PITCH + j);
                acc[r][0] += pv.x * v0.x + pv.y * v1.x + pv.z * v2.x + pv.w * v3.x;
                acc[r][1] += pv.x * v0.y + pv.y * v1.y + pv.z * v2.y + pv.w * v3.y;
                acc[r][2] += pv.x * v0.z + pv.y * v1.z + pv.z * v2.z + pv.w * v3.z;
                acc[r][3] += pv.x * v0.w + pv.y * v1.w + pv.z * v2.w + pv.w * v3.w;
            }
        }
        __syncthreads();   // protect Ks/Vs/Ss before next tile load
    }

    // ---- Epilogue: normalize and store ----
    #pragma unroll
    for (int r = 0; r < 4; r++) {
        float inv = 1.0f / lrow[ty * 4 + r];
        float4 o = make_float4(acc[r][0] * inv, acc[r][1] * inv,
                               acc[r][2] * inv, acc[r][3] * inv);
        *(float4*)(O + base + (size_t)(qt * BM + ty * 4 + r) * DHEAD + tx * 4) = o;
    }
}

extern "C" void kernel_launch(void* const* d_in, const int* in_sizes, int n_in,
                              void* d_out, int out_size) {
    const float* Q = (const float*)d_in[0];
    const float* K = (const float*)d_in[1];
    const float* V = (const float*)d_in[2];
    // d_in[3] = causal_mask flag (always 1 for this problem)
    float* O = (float*)d_out;

    const size_t smem_bytes = (size_t)(4 * BM * PITCH + 3 * BM) * sizeof(float); // 70400 B
    cudaFuncSetAttribute(mea_fp32_kernel,
                         cudaFuncAttributeMaxDynamicSharedMemorySize,
                         (int)smem_bytes);

    dim3 grid(SEQ / BM, NBH);   // (64 q-tiles, 64 batch*head)
    mea_fp32_kernel<<<grid, NTHREADS, smem_bytes>>>(Q, K, V, O);
}

// round 3
// speedup vs baseline: 6.2499x; 6.2499x over previous
#include <cuda_runtime.h>
#include <cuda_fp16.h>
#include <cstdint>
#include <math.h>

// Causal flash attention, B=4 H=16 S=4096 D=64, fp32 I/O.
// fp16 mma.sync.m16n8k16 (HMMA) with fp32 accumulation + fp32 online softmax.
// CTA: 128 threads (4 warps). BM=128 q rows (32 per warp), BN=64 k tile.

#define SEQ 4096
#define DH  64
#define BM  128
#define BN  64
#define NTH 128
#define QTILES (SEQ/BM)   // 32
#define NBH 64
#define KP  72            // smem pitch in halfs (conflict-free fragment loads)
#define NEG (-1.0e30f)

__device__ __forceinline__ void mma16816(float c[4], const uint32_t a[4],
                                         uint32_t b0, uint32_t b1) {
    asm volatile(
        "mma.sync.aligned.m16n8k16.row.col.f32.f16.f16.f32 "
        "{%0,%1,%2,%3}, {%4,%5,%6,%7}, {%8,%9}, {%0,%1,%2,%3};"
        : "+f"(c[0]), "+f"(c[1]), "+f"(c[2]), "+f"(c[3])
        : "r"(a[0]), "r"(a[1]), "r"(a[2]), "r"(a[3]), "r"(b0), "r"(b1));
}

__device__ __forceinline__ float qmax(float v) {   // max over 4-lane quad
    v = fmaxf(v, __shfl_xor_sync(0xffffffffu, v, 1));
    v = fmaxf(v, __shfl_xor_sync(0xffffffffu, v, 2));
    return v;
}
__device__ __forceinline__ float qsum(float v) {   // sum over 4-lane quad
    v += __shfl_xor_sync(0xffffffffu, v, 1);
    v += __shfl_xor_sync(0xffffffffu, v, 2);
    return v;
}

__global__ void __launch_bounds__(NTH)
fa_hmma_kernel(const float* __restrict__ Q, const float* __restrict__ K,
               const float* __restrict__ V, float* __restrict__ O) {
    __shared__ __align__(16) __half sbuf[2 * BN * KP];   // Ks | Vt (also Q staging)
    __half* Ks = sbuf;
    __half* Vt = sbuf + BN * KP;

    const int tid  = threadIdx.x;
    const int lane = tid & 31;
    const int wid  = tid >> 5;
    const int qt   = (QTILES - 1) - blockIdx.x;   // heavy CTAs first
    const int bh   = blockIdx.y;
    const size_t base = (size_t)bh * SEQ * DH;

    const int g = lane >> 2;        // 0..7  (row group)
    const int q = lane & 3;         // 0..3  (col quad)

    // ---- stage Q tile (128 rows x 64) into sbuf as fp16, pre-scaled ----
    {
        const float4* qr = (const float4*)(Q + base + (size_t)(qt * BM + tid) * DH);
        __half* dst = sbuf + tid * KP;
        #pragma unroll
        for (int c4 = 0; c4 < 16; c4++) {
            float4 f = qr[c4];
            *(__half2*)(dst + c4 * 4)     = __floats2half2_rn(f.x * 0.125f, f.y * 0.125f);
            *(__half2*)(dst + c4 * 4 + 2) = __floats2half2_rn(f.z * 0.125f, f.w * 0.125f);
        }
    }
    __syncthreads();

    // ---- build Q A-fragments in registers: 2 m-tiles x 4 k-chunks x 4 regs ----
    uint32_t qf[2][4][4];
    #pragma unroll
    for (int mt = 0; mt < 2; mt++) {
        const int r0 = wid * 32 + mt * 16 + g;
        #pragma unroll
        for (int kc = 0; kc < 4; kc++) {
            const int c0 = kc * 16 + q * 2;
            qf[mt][kc][0] = *(const uint32_t*)(sbuf + r0 * KP + c0);
            qf[mt][kc][1] = *(const uint32_t*)(sbuf + (r0 + 8) * KP + c0);
            qf[mt][kc][2] = *(const uint32_t*)(sbuf + r0 * KP + c0 + 8);
            qf[mt][kc][3] = *(const uint32_t*)(sbuf + (r0 + 8) * KP + c0 + 8);
        }
    }
    __syncthreads();

    float of[2][8][4];
    #pragma unroll
    for (int mt = 0; mt < 2; mt++)
        #pragma unroll
        for (int n = 0; n < 8; n++)
            #pragma unroll
            for (int j = 0; j < 4; j++) of[mt][n][j] = 0.0f;

    float m[2][2], l[2][2];
    #pragma unroll
    for (int mt = 0; mt < 2; mt++) { m[mt][0] = m[mt][1] = NEG; l[mt][0] = l[mt][1] = 0.0f; }

    const int ktmax = 2 * qt + 1;
    for (int kt = 0; kt <= ktmax; kt++) {
        // ---- load K tile -> Ks [kpos][d], fp16 ----
        {
            const int row = tid >> 1;
            const int d0  = (tid & 1) * 32;
            const float4* kr = (const float4*)(K + base + (size_t)(kt * BN + row) * DH + d0);
            __half* dst = Ks + row * KP + d0;
            #pragma unroll
            for (int c4 = 0; c4 < 8; c4++) {
                float4 f = kr[c4];
                *(__half2*)(dst + c4 * 4)     = __floats2half2_rn(f.x, f.y);
                *(__half2*)(dst + c4 * 4 + 2) = __floats2half2_rn(f.z, f.w);
            }
        }
        // ---- load V tile transposed -> Vt [d][kpos], fp16 ----
        {
            const int row = tid & 63;
            const int d0  = (tid >> 6) * 32;
            const float4* vr = (const float4*)(V + base + (size_t)(kt * BN + row) * DH + d0);
            #pragma unroll
            for (int c4 = 0; c4 < 8; c4++) {
                float4 f = vr[c4];
                const int d = d0 + c4 * 4;
                Vt[(d + 0) * KP + row] = __float2half_rn(f.x);
                Vt[(d + 1) * KP + row] = __float2half_rn(f.y);
                Vt[(d + 2) * KP + row] = __float2half_rn(f.z);
                Vt[(d + 3) * KP + row] = __float2half_rn(f.w);
            }
        }
        __syncthreads();

        // ---- S = Q @ K^T : c[2][8][4], B frags reused across both m-tiles ----
        float c[2][8][4];
        #pragma unroll
        for (int mt = 0; mt < 2; mt++)
            #pragma unroll
            for (int n = 0; n < 8; n++)
                #pragma unroll
                for (int j = 0; j < 4; j++) c[mt][n][j] = 0.0f;

        #pragma unroll
        for (int kc = 0; kc < 4; kc++) {
            #pragma unroll
            for (int n = 0; n < 8; n++) {
                const __half* bp = Ks + (n * 8 + g) * KP + kc * 16 + q * 2;
                uint32_t b0 = *(const uint32_t*)bp;
                uint32_t b1 = *(const uint32_t*)(bp + 8);
                mma16816(c[0][n], qf[0][kc], b0, b1);
                mma16816(c[1][n], qf[1][kc], b0, b1);
            }
        }

        // ---- online softmax + pack P fragments ----
        uint32_t pf[2][4][4];
        #pragma unroll
        for (int mt = 0; mt < 2; mt++) {
            const int rw = qt * BM + wid * 32 + mt * 16;    // warp m-tile base row
            const int rg0 = rw + g, rg1 = rw + g + 8;

            if (kt * BN + BN - 1 > rw) {                    // tile crosses diagonal
                #pragma unroll
                for (int n = 0; n < 8; n++) {
                    const int col = kt * BN + n * 8 + q * 2;
                    if (col     > rg0) c[mt][n][0] = NEG;
                    if (col + 1 > rg0) c[mt][n][1] = NEG;
                    if (col     > rg1) c[mt][n][2] = NEG;
                    if (col + 1 > rg1) c[mt][n][3] = NEG;
                }
            }

            float mx0 = NEG, mx1 = NEG;
            #pragma unroll
            for (int n = 0; n < 8; n++) {
                mx0 = fmaxf(mx0, fmaxf(c[mt][n][0], c[mt][n][1]));
                mx1 = fmaxf(mx1, fmaxf(c[mt][n][2], c[mt][n][3]));
            }
            mx0 = qmax(mx0); mx1 = qmax(mx1);

            const float mn0 = fmaxf(m[mt][0], mx0);
            const float mn1 = fmaxf(m[mt][1], mx1);
            const float a0 = __expf(m[mt][0] - mn0);
            const float a1 = __expf(m[mt][1] - mn1);

            float s0 = 0.0f, s1 = 0.0f;
            #pragma unroll
            for (int n = 0; n < 8; n++) {
                float e0 = __expf(c[mt][n][0] - mn0);
                float e1 = __expf(c[mt][n][1] - mn0);
                float e2 = __expf(c[mt][n][2] - mn1);
                float e3 = __expf(c[mt][n][3] - mn1);
                s0 += e0 + e1; s1 += e2 + e3;
                c[mt][n][0] = e0; c[mt][n][1] = e1; c[mt][n][2] = e2; c[mt][n][3] = e3;
            }
            s0 = qsum(s0); s1 = qsum(s1);

            l[mt][0] = l[mt][0] * a0 + s0;  m[mt][0] = mn0;
            l[mt][1] = l[mt][1] * a1 + s1;  m[mt][1] = mn1;

            // rescale O accumulator
            #pragma unroll
            for (int n = 0; n < 8; n++) {
                of[mt][n][0] *= a0; of[mt][n][1] *= a0;
                of[mt][n][2] *= a1; of[mt][n][3] *= a1;
            }
            // pack P: C(m16n8) layout == A(m16k16) layout, in registers
            #pragma unroll
            for (int kc = 0; kc < 4; kc++) {
                __half2 h0 = __floats2half2_rn(c[mt][2*kc][0],   c[mt][2*kc][1]);
                __half2 h1 = __floats2half2_rn(c[mt][2*kc][2],   c[mt][2*kc][3]);
                __half2 h2 = __floats2half2_rn(c[mt][2*kc+1][0], c[mt][2*kc+1][1]);
                __half2 h3 = __floats2half2_rn(c[mt][2*kc+1][2], c[mt][2*kc+1][3]);
                pf[mt][kc][0] = *(uint32_t*)&h0;
                pf[mt][kc][1] = *(uint32_t*)&h1;
                pf[mt][kc][2] = *(uint32_t*)&h2;
                pf[mt][kc][3] = *(uint32_t*)&h3;
            }
        }

        // ---- O += P @ V : B frags from Vt, reused across both m-tiles ----
        #pragma unroll
        for (int kc = 0; kc < 4; kc++) {
            #pragma unroll
            for (int n = 0; n < 8; n++) {
                const __half* bp = Vt + (n * 8 + g) * KP + kc * 16 + q * 2;
                uint32_t b0 = *(const uint32_t*)bp;
                uint32_t b1 = *(const uint32_t*)(bp + 8);
                mma16816(of[0][n], pf[0][kc], b0, b1);
                mma16816(of[1][n], pf[1][kc], b0, b1);
            }
        }
        __syncthreads();
    }

    // ---- epilogue: normalize, store fp32 ----
    #pragma unroll
    for (int mt = 0; mt < 2; mt++) {
        const int rg0 = qt * BM + wid * 32 + mt * 16 + g;
        const float inv0 = 1.0f / l[mt][0];
        const float inv1 = 1.0f / l[mt][1];
        float* o0 = O + base + (size_t)rg0 * DH + q * 2;
        float* o1 = o0 + 8 * DH;
        #pragma unroll
        for (int n = 0; n < 8; n++) {
            *(float2*)(o0 + n * 8) = make_float2(of[mt][n][0] * inv0, of[mt][n][1] * inv0);
            *(float2*)(o1 + n * 8) = make_float2(of[mt][n][2] * inv1, of[mt][n][3] * inv1);
        }
    }
}

extern "C" void kernel_launch(void* const* d_in, const int* in_sizes, int n_in,
                              void* d_out, int out_size) {
    const float* Q = (const float*)d_in[0];
    const float* K = (const float*)d_in[1];
    const float* V = (const float*)d_in[2];
    float* O = (float*)d_out;

    dim3 grid(QTILES, NBH);
    fa_hmma_kernel<<<grid, NTH>>>(Q, K, V, O);
}

// round 4
// speedup vs baseline: 7.5696x; 1.2111x over previous
#include <cuda_runtime.h>
#include <cuda_fp16.h>
#include <cstdint>
#include <math.h>

// Causal flash attention, B=4 H=16 S=4096 D=64, fp32 I/O.
// fp16 mma.sync.m16n8k16 + ldmatrix fragments + double-buffered K/V pipeline.
// CTA: 128 threads (4 warps), BM=128 q rows (32/warp), BN=64 k tile.

#define SEQ 4096
#define DH  64
#define BM  128
#define BN  64
#define NTH 128
#define QTILES (SEQ/BM)   // 32
#define NBH 64
#define KP  72            // smem pitch in halfs (144B rows: LDSM conflict-free)
#define NEG (-1.0e30f)
// scale = (1/sqrt(64)) * log2(e)  -> softmax in exp2 domain
#define QSCALE 0.1803368801111204f

__device__ __forceinline__ uint32_t s_u32(const void* p) {
    uint32_t a;
    asm("{ .reg .u64 t; cvta.to.shared.u64 t, %1; cvt.u32.u64 %0, t; }" : "=r"(a) : "l"(p));
    return a;
}
__device__ __forceinline__ float ex2(float x) {
    float y; asm("ex2.approx.f32 %0, %1;" : "=f"(y) : "f"(x)); return y;
}
#define LDSM4(r0,r1,r2,r3,a) \
    asm volatile("ldmatrix.sync.aligned.m8n8.x4.shared.b16 {%0,%1,%2,%3}, [%4];" \
                 : "=r"(r0), "=r"(r1), "=r"(r2), "=r"(r3) : "r"(a))
#define LDSM4T(r0,r1,r2,r3,a) \
    asm volatile("ldmatrix.sync.aligned.m8n8.x4.trans.shared.b16 {%0,%1,%2,%3}, [%4];" \
                 : "=r"(r0), "=r"(r1), "=r"(r2), "=r"(r3) : "r"(a))

__device__ __forceinline__ void mma16816(float c[4], const uint32_t a[4],
                                         uint32_t b0, uint32_t b1) {
    asm volatile(
        "mma.sync.aligned.m16n8k16.row.col.f32.f16.f16.f32 "
        "{%0,%1,%2,%3}, {%4,%5,%6,%7}, {%8,%9}, {%0,%1,%2,%3};"
        : "+f"(c[0]), "+f"(c[1]), "+f"(c[2]), "+f"(c[3])
        : "r"(a[0]), "r"(a[1]), "r"(a[2]), "r"(a[3]), "r"(b0), "r"(b1));
}

__device__ __forceinline__ float qmax4(float v) {
    v = fmaxf(v, __shfl_xor_sync(0xffffffffu, v, 1));
    v = fmaxf(v, __shfl_xor_sync(0xffffffffu, v, 2));
    return v;
}
__device__ __forceinline__ float qsum4(float v) {
    v += __shfl_xor_sync(0xffffffffu, v, 1);
    v += __shfl_xor_sync(0xffffffffu, v, 2);
    return v;
}
__device__ __forceinline__ uint4 pack8(float4 a, float4 b) {
    __half2 h0 = __floats2half2_rn(a.x, a.y), h1 = __floats2half2_rn(a.z, a.w);
    __half2 h2 = __floats2half2_rn(b.x, b.y), h3 = __floats2half2_rn(b.z, b.w);
    return make_uint4(*(uint32_t*)&h0, *(uint32_t*)&h1, *(uint32_t*)&h2, *(uint32_t*)&h3);
}

__global__ void __launch_bounds__(NTH)
fa_hmma2_kernel(const float* __restrict__ Q, const float* __restrict__ K,
                const float* __restrict__ V, float* __restrict__ O) {
    __shared__ __align__(16) __half KsB[2][BN * KP];
    __shared__ __align__(16) __half VsB[2][BN * KP];

    const int tid  = threadIdx.x;
    const int lane = tid & 31;
    const int wid  = tid >> 5;
    const int qt   = (QTILES - 1) - blockIdx.x;   // heavy CTAs first
    const int bh   = blockIdx.y;
    const size_t base = (size_t)bh * SEQ * DH;
    const float* Kb = K + base;
    const float* Vb = V + base;

    const int g = lane >> 2;        // 0..7
    const int q = lane & 3;         // 0..3

    // ---- stage Q (128 x 64) as fp16 across KsB[0..1] viewed as 128 rows ----
    {
        const float4* qr = (const float4*)(Q + base + (size_t)(qt * BM + tid) * DH);
        __half* dst = &KsB[0][0] + tid * KP;
        #pragma unroll
        for (int c8 = 0; c8 < 8; c8++) {
            float4 f0 = qr[2 * c8], f1 = qr[2 * c8 + 1];
            f0.x *= QSCALE; f0.y *= QSCALE; f0.z *= QSCALE; f0.w *= QSCALE;
            f1.x *= QSCALE; f1.y *= QSCALE; f1.z *= QSCALE; f1.w *= QSCALE;
            *(uint4*)(dst + c8 * 8) = pack8(f0, f1);
        }
    }
    __syncthreads();

    // ---- Q A-fragments via ldmatrix: 2 m-tiles x 4 k-chunks x 4 regs ----
    uint32_t qf[2][4][4];
    {
        const uint32_t qbase = s_u32(&KsB[0][0]);
        const int lrow = ((lane >> 3) & 1) * 8 + (lane & 7);
        const int lcol = ((lane >> 4) & 1) * 8;
        #pragma unroll
        for (int mt = 0; mt < 2; mt++)
            #pragma unroll
            for (int kc = 0; kc < 4; kc++) {
                uint32_t a = qbase +
                    (uint32_t)(((wid * 32 + mt * 16 + lrow) * KP + kc * 16 + lcol) * 2);
                LDSM4(qf[mt][kc][0], qf[mt][kc][1], qf[mt][kc][2], qf[mt][kc][3], a);
            }
    }
    __syncthreads();

    // ---- preload tile 0 into buffer 0 ----
    const int lrowT = tid >> 1;
    const int ld0   = (tid & 1) * 32;
    {
        const float4* kr = (const float4*)(Kb + (size_t)lrowT * DH + ld0);
        const float4* vr = (const float4*)(Vb + (size_t)lrowT * DH + ld0);
        __half* kd = &KsB[0][0] + lrowT * KP + ld0;
        __half* vd = &VsB[0][0] + lrowT * KP + ld0;
        #pragma unroll
        for (int c = 0; c < 4; c++) {
            *(uint4*)(kd + c * 8) = pack8(kr[2 * c], kr[2 * c + 1]);
            *(uint4*)(vd + c * 8) = pack8(vr[2 * c], vr[2 * c + 1]);
        }
    }
    __syncthreads();

    float of[2][8][4];
    #pragma unroll
    for (int mt = 0; mt < 2; mt++)
        #pragma unroll
        for (int n = 0; n < 8; n++)
            #pragma unroll
            for (int j = 0; j < 4; j++) of[mt][n][j] = 0.0f;
    float m[2][2], l[2][2];
    #pragma unroll
    for (int mt = 0; mt < 2; mt++) { m[mt][0] = m[mt][1] = NEG; l[mt][0] = l[mt][1] = 0.0f; }

    // hoisted lane offsets for B-fragment ldmatrix
    const uint32_t qkOff = (uint32_t)(((((lane >> 4) & 1) * 8 + (lane & 7)) * KP
                                       + ((lane >> 3) & 1) * 8) * 2);
    const uint32_t pvOff = (uint32_t)(((((lane >> 3) & 1) * 8 + (lane & 7)) * KP
                                       + ((lane >> 4) & 1) * 8) * 2);

    const int ktmax = 2 * qt + 1;
    for (int kt = 0; kt <= ktmax; kt++) {
        const uint32_t ksb = s_u32(&KsB[kt & 1][0]);
        const uint32_t vsb = s_u32(&VsB[kt & 1][0]);
        __half* Kn = &KsB[(kt + 1) & 1][0];
        __half* Vn = &VsB[(kt + 1) & 1][0];
        const bool hasnext = (kt < ktmax);

        // ---- prefetch next K (gmem -> regs) ----
        float4 kreg[8];
        if (hasnext) {
            const float4* kr = (const float4*)(Kb + (size_t)((kt + 1) * BN + lrowT) * DH + ld0);
            #pragma unroll
            for (int c = 0; c < 8; c++) kreg[c] = kr[c];
        }

        // ---- S = Q @ K^T ----
        float c[2][8][4];
        #pragma unroll
        for (int mt = 0; mt < 2; mt++)
            #pragma unroll
            for (int n = 0; n < 8; n++)
                #pragma unroll
                for (int j = 0; j < 4; j++) c[mt][n][j] = 0.0f;

        #pragma unroll
        for (int kc = 0; kc < 4; kc++)
            #pragma unroll
            for (int jp = 0; jp < 4; jp++) {
                uint32_t b00, b01, b10, b11;
                uint32_t a = ksb + qkOff + (uint32_t)((jp * 16 * KP + kc * 16) * 2);
                LDSM4(b00, b01, b10, b11, a);
                mma16816(c[0][2 * jp],     qf[0][kc], b00, b01);
                mma16816(c[1][2 * jp],     qf[1][kc], b00, b01);
                mma16816(c[0][2 * jp + 1], qf[0][kc], b10, b11);
                mma16816(c[1][2 * jp + 1], qf[1][kc], b10, b11);
            }

        // ---- store K prefetch, start V prefetch ----
        if (hasnext) {
            __half* kd = Kn + lrowT * KP + ld0;
            #pragma unroll
            for (int cc = 0; cc < 4; cc++)
                *(uint4*)(kd + cc * 8) = pack8(kreg[2 * cc], kreg[2 * cc + 1]);
        }
        float4 vreg[8];
        if (hasnext) {
            const float4* vr = (const float4*)(Vb + (size_t)((kt + 1) * BN + lrowT) * DH + ld0);
            #pragma unroll
            for (int cc = 0; cc < 8; cc++) vreg[cc] = vr[cc];
        }

        // ---- online softmax (exp2 domain) + pack P fragments ----
        uint32_t pfr[2][4][4];
        #pragma unroll
        for (int mt = 0; mt < 2; mt++) {
            const int rw = qt * BM + wid * 32 + mt * 16;
            const int rg0 = rw + g, rg1 = rw + g + 8;

            if (kt * BN + BN - 1 > rw) {
                #pragma unroll
                for (int n = 0; n < 8; n++) {
                    const int col = kt * BN + n * 8 + q * 2;
                    if (col     > rg0) c[mt][n][0] = NEG;
                    if (col + 1 > rg0) c[mt][n][1] = NEG;
                    if (col     > rg1) c[mt][n][2] = NEG;
                    if (col + 1 > rg1) c[mt][n][3] = NEG;
                }
            }

            float mx0 = NEG, mx1 = NEG;
            #pragma unroll
            for (int n = 0; n < 8; n++) {
                mx0 = fmaxf(mx0, fmaxf(c[mt][n][0], c[mt][n][1]));
                mx1 = fmaxf(mx1, fmaxf(c[mt][n][2], c[mt][n][3]));
            }
            mx0 = qmax4(mx0); mx1 = qmax4(mx1);

            const float mn0 = fmaxf(m[mt][0], mx0);
            const float mn1 = fmaxf(m[mt][1], mx1);
            const float a0 = ex2(m[mt][0] - mn0);
            const float a1 = ex2(m[mt][1] - mn1);

            float s0 = 0.0f, s1 = 0.0f;
            #pragma unroll
            for (int n = 0; n < 8; n++) {
                float e0 = ex2(c[mt][n][0] - mn0);
                float e1 = ex2(c[mt][n][1] - mn0);
                float e2 = ex2(c[mt][n][2] - mn1);
                float e3 = ex2(c[mt][n][3] - mn1);
                s0 += e0 + e1; s1 += e2 + e3;
                c[mt][n][0] = e0; c[mt][n][1] = e1; c[mt][n][2] = e2; c[mt][n][3] = e3;
            }
            s0 = qsum4(s0); s1 = qsum4(s1);

            l[mt][0] = l[mt][0] * a0 + s0;  m[mt][0] = mn0;
            l[mt][1] = l[mt][1] * a1 + s1;  m[mt][1] = mn1;

            #pragma unroll
            for (int n = 0; n < 8; n++) {
                of[mt][n][0] *= a0; of[mt][n][1] *= a0;
                of[mt][n][2] *= a1; of[mt][n][3] *= a1;
            }
            #pragma unroll
            for (int kc = 0; kc < 4; kc++) {
                __half2 h0 = __floats2half2_rn(c[mt][2*kc][0],   c[mt][2*kc][1]);
                __half2 h1 = __floats2half2_rn(c[mt][2*kc][2],   c[mt][2*kc][3]);
                __half2 h2 = __floats2half2_rn(c[mt][2*kc+1][0], c[mt][2*kc+1][1]);
                __half2 h3 = __floats2half2_rn(c[mt][2*kc+1][2], c[mt][2*kc+1][3]);
                pfr[mt][kc][0] = *(uint32_t*)&h0;
                pfr[mt][kc][1] = *(uint32_t*)&h1;
                pfr[mt][kc][2] = *(uint32_t*)&h2;
                pfr[mt][kc][3] = *(uint32_t*)&h3;
            }
        }

        // ---- store V prefetch ----
        if (hasnext) {
            __half* vd = Vn + lrowT * KP + ld0;
            #pragma unroll
            for (int cc = 0; cc < 4; cc++)
                *(uint4*)(vd + cc * 8) = pack8(vreg[2 * cc], vreg[2 * cc + 1]);
        }

        // ---- O += P @ V  (B-frags via ldmatrix.trans from row-major V) ----
        #pragma unroll
        for (int kc = 0; kc < 4; kc++)
            #pragma unroll
            for (int jp = 0; jp < 4; jp++) {
                uint32_t b00, b01, b10, b11;
                uint32_t a = vsb + pvOff + (uint32_t)((kc * 16 * KP + jp * 16) * 2);
                LDSM4T(b00, b01, b10, b11, a);
                mma16816(of[0][2 * jp],     pfr[0][kc], b00, b01);
                mma16816(of[1][2 * jp],     pfr[1][kc], b00, b01);
                mma16816(of[0][2 * jp + 1], pfr[0][kc], b10, b11);
                mma16816(of[1][2 * jp + 1], pfr[1][kc], b10, b11);
            }
        __syncthreads();
    }

    // ---- epilogue: normalize, store fp32 ----
    #pragma unroll
    for (int mt = 0; mt < 2; mt++) {
        const int rg0 = qt * BM + wid * 32 + mt * 16 + g;
        const float inv0 = 1.0f / l[mt][0];
        const float inv1 = 1.0f / l[mt][1];
        float* o0 = O + base + (size_t)rg0 * DH + q * 2;
        float* o1 = o0 + 8 * DH;
        #pragma unroll
        for (int n = 0; n < 8; n++) {
            *(float2*)(o0 + n * 8) = make_float2(of[mt][n][0] * inv0, of[mt][n][1] * inv0);
            *(float2*)(o1 + n * 8) = make_float2(of[mt][n][2] * inv1, of[mt][n][3] * inv1);
        }
    }
}

extern "C" void kernel_launch(void* const* d_in, const int* in_sizes, int n_in,
                              void* d_out, int out_size) {
    const float* Q = (const float*)d_in[0];
    const float* K = (const float*)d_in[1];
    const float* V = (const float*)d_in[2];
    float* O = (float*)d_out;

    dim3 grid(QTILES, NBH);
    fa_hmma2_kernel<<<grid, NTH>>>(Q, K, V, O);
}

// round 5
// speedup vs baseline: 11.3378x; 1.4978x over previous
#include <cuda_runtime.h>
#include <cuda_fp16.h>
#include <cstdint>
#include <math.h>

// Causal flash attention, B=4 H=16 S=4096 D=64, fp32 I/O.
// R5: pre-convert Q/K/V to fp16 in gmem; cp.async 4-buffer ring (distance 2),
// one barrier per tile; fp16 mma.sync.m16n8k16 + ldmatrix; exp2 softmax.

#define SEQ 4096
#define DH  64
#define BM  128
#define BN  64
#define NTH 128
#define QTILES (SEQ/BM)   // 32
#define NBH 64
#define KP  72            // smem pitch in halfs (144B rows: LDSM conflict-free)
#define NEG (-1.0e30f)
#define QSCALE 0.1803368801111204f   // (1/sqrt(64)) * log2(e)
#define NELEM (4*16*4096*64)         // 16777216
#define TILEH (BN * KP)              // halfs per tile per tensor (4608)

__device__ __half g_qh[NELEM];
__device__ __half g_kh[NELEM];
__device__ __half g_vh[NELEM];

__device__ __forceinline__ uint32_t s_u32(const void* p) {
    uint32_t a;
    asm("{ .reg .u64 t; cvta.to.shared.u64 t, %1; cvt.u32.u64 %0, t; }" : "=r"(a) : "l"(p));
    return a;
}
__device__ __forceinline__ float ex2(float x) {
    float y; asm("ex2.approx.f32 %0, %1;" : "=f"(y) : "f"(x)); return y;
}
#define LDSM4(r0,r1,r2,r3,a) \
    asm volatile("ldmatrix.sync.aligned.m8n8.x4.shared.b16 {%0,%1,%2,%3}, [%4];" \
                 : "=r"(r0), "=r"(r1), "=r"(r2), "=r"(r3) : "r"(a))
#define LDSM4T(r0,r1,r2,r3,a) \
    asm volatile("ldmatrix.sync.aligned.m8n8.x4.trans.shared.b16 {%0,%1,%2,%3}, [%4];" \
                 : "=r"(r0), "=r"(r1), "=r"(r2), "=r"(r3) : "r"(a))
#define CPA16(dst, src) \
    asm volatile("cp.async.cg.shared.global [%0], [%1], 16;" :: "r"(dst), "l"(src))
#define CPCOMMIT() asm volatile("cp.async.commit_group;" ::: "memory")
#define CPWAIT(n)  asm volatile("cp.async.wait_group %0;" :: "n"(n) : "memory")

__device__ __forceinline__ void mma16816(float c[4], const uint32_t a[4],
                                         uint32_t b0, uint32_t b1) {
    asm volatile(
        "mma.sync.aligned.m16n8k16.row.col.f32.f16.f16.f32 "
        "{%0,%1,%2,%3}, {%4,%5,%6,%7}, {%8,%9}, {%0,%1,%2,%3};"
        : "+f"(c[0]), "+f"(c[1]), "+f"(c[2]), "+f"(c[3])
        : "r"(a[0]), "r"(a[1]), "r"(a[2]), "r"(a[3]), "r"(b0), "r"(b1));
}

__device__ __forceinline__ float qmax4(float v) {
    v = fmaxf(v, __shfl_xor_sync(0xffffffffu, v, 1));
    v = fmaxf(v, __shfl_xor_sync(0xffffffffu, v, 2));
    return v;
}
__device__ __forceinline__ float qsum4(float v) {
    v += __shfl_xor_sync(0xffffffffu, v, 1);
    v += __shfl_xor_sync(0xffffffffu, v, 2);
    return v;
}
__device__ __forceinline__ uint4 pack8(float4 a, float4 b) {
    __half2 h0 = __floats2half2_rn(a.x, a.y), h1 = __floats2half2_rn(a.z, a.w);
    __half2 h2 = __floats2half2_rn(b.x, b.y), h3 = __floats2half2_rn(b.z, b.w);
    return make_uint4(*(uint32_t*)&h0, *(uint32_t*)&h1, *(uint32_t*)&h2, *(uint32_t*)&h3);
}

// ---- pre-pass: fp32 -> fp16 (Q scaled) ----
__global__ void __launch_bounds__(256)
conv_kernel(const float* __restrict__ Q, const float* __restrict__ K,
            const float* __restrict__ V) {
    const size_t i = ((size_t)blockIdx.x * 256 + threadIdx.x) * 8;
    if (i >= NELEM) return;
    float4 a = *(const float4*)(Q + i), b = *(const float4*)(Q + i + 4);
    a.x *= QSCALE; a.y *= QSCALE; a.z *= QSCALE; a.w *= QSCALE;
    b.x *= QSCALE; b.y *= QSCALE; b.z *= QSCALE; b.w *= QSCALE;
    *(uint4*)(g_qh + i) = pack8(a, b);
    *(uint4*)(g_kh + i) = pack8(*(const float4*)(K + i), *(const float4*)(K + i + 4));
    *(uint4*)(g_vh + i) = pack8(*(const float4*)(V + i), *(const float4*)(V + i + 4));
}

// copy one 64x64 fp16 tile (K and V) into ring buffer b via cp.async
__device__ __forceinline__ void tile_cpasync(uint32_t smK, uint32_t smV,
                                             const __half* gK, const __half* gV,
                                             int tid) {
    const int row = tid >> 1;
    const int hc  = (tid & 1) * 32;            // half offset within row
    const uint32_t dK = smK + (uint32_t)(row * KP + hc) * 2;
    const uint32_t dV = smV + (uint32_t)(row * KP + hc) * 2;
    const __half* sK = gK + (size_t)row * DH + hc;
    const __half* sV = gV + (size_t)row * DH + hc;
    #pragma unroll
    for (int c = 0; c < 4; c++) {
        CPA16(dK + c * 16, sK + c * 8);
        CPA16(dV + c * 16, sV + c * 8);
    }
}

__global__ void __launch_bounds__(NTH)
fa_hmma3_kernel(float* __restrict__ O) {
    extern __shared__ __align__(16) __half sm[];   // 4 bufs x (K tile | V tile)

    const int tid  = threadIdx.x;
    const int lane = tid & 31;
    const int wid  = tid >> 5;
    const int qt   = (QTILES - 1) - blockIdx.x;   // heavy CTAs first
    const int bh   = blockIdx.y;
    const size_t base = (size_t)bh * SEQ * DH;
    const __half* Kb = g_kh + base;
    const __half* Vb = g_vh + base;

    const int g = lane >> 2;        // 0..7
    const int q = lane & 3;         // 0..3
    const uint32_t smb = s_u32(sm);

    // ---- stage Q tile via cp.async into buf0/1 region, extract fragments ----
    {
        const __half* qsrc = g_qh + base + (size_t)(qt * BM + tid) * DH;
        const uint32_t qdst = smb + (uint32_t)(tid * KP) * 2;
        #pragma unroll
        for (int c = 0; c < 8; c++) CPA16(qdst + c * 16, qsrc + c * 8);
        CPCOMMIT(); CPWAIT(0);
    }
    __syncthreads();

    uint32_t qf[2][4][4];
    {
        const int lrow = ((lane >> 3) & 1) * 8 + (lane & 7);
        const int lcol = ((lane >> 4) & 1) * 8;
        #pragma unroll
        for (int mt = 0; mt < 2; mt++)
            #pragma unroll
            for (int kc = 0; kc < 4; kc++) {
                uint32_t a = smb +
                    (uint32_t)(((wid * 32 + mt * 16 + lrow) * KP + kc * 16 + lcol) * 2);
                LDSM4(qf[mt][kc][0], qf[mt][kc][1], qf[mt][kc][2], qf[mt][kc][3], a);
            }
    }
    __syncthreads();   // done reading Q staging before K/V overwrite it

    const int ktmax = 2 * qt + 1;   // >= 1 always

    // ---- preload tiles 0 and 1 ----
    tile_cpasync(smb + 0 * (2 * TILEH * 2), smb + (0 * 2 + 1) * TILEH * 2,
                 Kb, Vb, tid);
    CPCOMMIT();
    tile_cpasync(smb + 1 * (2 * TILEH * 2), smb + (1 * 2 + 1) * TILEH * 2,
                 Kb + (size_t)BN * DH, Vb + (size_t)BN * DH, tid);
    CPCOMMIT();

    float of[2][8][4];
    #pragma unroll
    for (int mt = 0; mt < 2; mt++)
        #pragma unroll
        for (int n = 0; n < 8; n++)
            #pragma unroll
            for (int j = 0; j < 4; j++) of[mt][n][j] = 0.0f;
    float m[2][2], l[2][2];
    #pragma unroll
    for (int mt = 0; mt < 2; mt++) { m[mt][0] = m[mt][1] = NEG; l[mt][0] = l[mt][1] = 0.0f; }

    const uint32_t qkOff = (uint32_t)(((((lane >> 4) & 1) * 8 + (lane & 7)) * KP
                                       + ((lane >> 3) & 1) * 8) * 2);
    const uint32_t pvOff = (uint32_t)(((((lane >> 3) & 1) * 8 + (lane & 7)) * KP
                                       + ((lane >> 4) & 1) * 8) * 2);

    for (int kt = 0; kt <= ktmax; kt++) {
        const int b = kt & 3;
        const uint32_t ksb = smb + (uint32_t)(b * 2) * TILEH * 2;
        const uint32_t vsb = ksb + TILEH * 2;

        // issue prefetch for tile kt+2 into buffer (kt+2)&3
        const int rem = ktmax - kt;
        if (rem >= 2) {
            const int nb = (kt + 2) & 3;
            tile_cpasync(smb + (uint32_t)(nb * 2) * TILEH * 2,
                         smb + (uint32_t)(nb * 2 + 1) * TILEH * 2,
                         Kb + (size_t)(kt + 2) * BN * DH,
                         Vb + (size_t)(kt + 2) * BN * DH, tid);
            CPCOMMIT();
        }
        if (rem >= 2)      CPWAIT(2);
        else if (rem == 1) CPWAIT(1);
        else               CPWAIT(0);
        __syncthreads();

        // ---- S = Q @ K^T ----
        float c[2][8][4];
        #pragma unroll
        for (int mt = 0; mt < 2; mt++)
            #pragma unroll
            for (int n = 0; n < 8; n++)
                #pragma unroll
                for (int j = 0; j < 4; j++) c[mt][n][j] = 0.0f;

        #pragma unroll
        for (int kc = 0; kc < 4; kc++)
            #pragma unroll
            for (int jp = 0; jp < 4; jp++) {
                uint32_t b00, b01, b10, b11;
                uint32_t a = ksb + qkOff + (uint32_t)((jp * 16 * KP + kc * 16) * 2);
                LDSM4(b00, b01, b10, b11, a);
                mma16816(c[0][2 * jp],     qf[0][kc], b00, b01);
                mma16816(c[1][2 * jp],     qf[1][kc], b00, b01);
                mma16816(c[0][2 * jp + 1], qf[0][kc], b10, b11);
                mma16816(c[1][2 * jp + 1], qf[1][kc], b10, b11);
            }

        // ---- online softmax (exp2 domain) + pack P fragments ----
        uint32_t pfr[2][4][4];
        #pragma unroll
        for (int mt = 0; mt < 2; mt++) {
            const int rw = qt * BM + wid * 32 + mt * 16;
            const int rg0 = rw + g, rg1 = rw + g + 8;

            if (kt * BN + BN - 1 > rw) {
                #pragma unroll
                for (int n = 0; n < 8; n++) {
                    const int col = kt * BN + n * 8 + q * 2;
                    if (col     > rg0) c[mt][n][0] = NEG;
                    if (col + 1 > rg0) c[mt][n][1] = NEG;
                    if (col     > rg1) c[mt][n][2] = NEG;
                    if (col + 1 > rg1) c[mt][n][3] = NEG;
                }
            }

            float mx0 = NEG, mx1 = NEG;
            #pragma unroll
            for (int n = 0; n < 8; n++) {
                mx0 = fmaxf(mx0, fmaxf(c[mt][n][0], c[mt][n][1]));
                mx1 = fmaxf(mx1, fmaxf(c[mt][n][2], c[mt][n][3]));
            }
            mx0 = qmax4(mx0); mx1 = qmax4(mx1);

            const float mn0 = fmaxf(m[mt][0], mx0);
            const float mn1 = fmaxf(m[mt][1], mx1);
            const float a0 = ex2(m[mt][0] - mn0);
            const float a1 = ex2(m[mt][1] - mn1);

            float s0 = 0.0f, s1 = 0.0f;
            #pragma unroll
            for (int n = 0; n < 8; n++) {
                float e0 = ex2(c[mt][n][0] - mn0);
                float e1 = ex2(c[mt][n][1] - mn0);
                float e2 = ex2(c[mt][n][2] - mn1);
                float e3 = ex2(c[mt][n][3] - mn1);
                s0 += e0 + e1; s1 += e2 + e3;
                c[mt][n][0] = e0; c[mt][n][1] = e1; c[mt][n][2] = e2; c[mt][n][3] = e3;
            }
            s0 = qsum4(s0); s1 = qsum4(s1);

            l[mt][0] = l[mt][0] * a0 + s0;  m[mt][0] = mn0;
            l[mt][1] = l[mt][1] * a1 + s1;  m[mt][1] = mn1;

            #pragma unroll
            for (int n = 0; n < 8; n++) {
                of[mt][n][0] *= a0; of[mt][n][1] *= a0;
                of[mt][n][2] *= a1; of[mt][n][3] *= a1;
            }
            #pragma unroll
            for (int kc = 0; kc < 4; kc++) {
                __half2 h0 = __floats2half2_rn(c[mt][2*kc][0],   c[mt][2*kc][1]);
                __half2 h1 = __floats2half2_rn(c[mt][2*kc][2],   c[mt][2*kc][3]);
                __half2 h2 = __floats2half2_rn(c[mt][2*kc+1][0], c[mt][2*kc+1][1]);
                __half2 h3 = __floats2half2_rn(c[mt][2*kc+1][2], c[mt][2*kc+1][3]);
                pfr[mt][kc][0] = *(uint32_t*)&h0;
                pfr[mt][kc][1] = *(uint32_t*)&h1;
                pfr[mt][kc][2] = *(uint32_t*)&h2;
                pfr[mt][kc][3] = *(uint32_t*)&h3;
            }
        }

        // ---- O += P @ V  (ldmatrix.trans from row-major V) ----
        #pragma unroll
        for (int kc = 0; kc < 4; kc++)
            #pragma unroll
            for (int jp = 0; jp < 4; jp++) {
                uint32_t b00, b01, b10, b11;
                uint32_t a = vsb + pvOff + (uint32_t)((kc * 16 * KP + jp * 16) * 2);
                LDSM4T(b00, b01, b10, b11, a);
                mma16816(of[0][2 * jp],     pfr[0][kc], b00, b01);
                mma16816(of[1][2 * jp],     pfr[1][kc], b00, b01);
                mma16816(of[0][2 * jp + 1], pfr[0][kc], b10, b11);
                mma16816(of[1][2 * jp + 1], pfr[1][kc], b10, b11);
            }
        // no trailing barrier: next iter writes buf (kt+3)&3, never the
        // buffer any warp can still be reading (distance-2, 4-buffer ring)
    }

    // ---- epilogue: normalize, store fp32 ----
    #pragma unroll
    for (int mt = 0; mt < 2; mt++) {
        const int rg0 = qt * BM + wid * 32 + mt * 16 + g;
        const float inv0 = 1.0f / l[mt][0];
        const float inv1 = 1.0f / l[mt][1];
        float* o0 = O + base + (size_t)rg0 * DH + q * 2;
        float* o1 = o0 + 8 * DH;
        #pragma unroll
        for (int n = 0; n < 8; n++) {
            *(float2*)(o0 + n * 8) = make_float2(of[mt][n][0] * inv0, of[mt][n][1] * inv0);
            *(float2*)(o1 + n * 8) = make_float2(of[mt][n][2] * inv1, of[mt][n][3] * inv1);
        }
    }
}

extern "C" void kernel_launch(void* const* d_in, const int* in_sizes, int n_in,
                              void* d_out, int out_size) {
    const float* Q = (const float*)d_in[0];
    const float* K = (const float*)d_in[1];
    const float* V = (const float*)d_in[2];
    float* O = (float*)d_out;

    conv_kernel<<<NELEM / 8 / 256, 256>>>(Q, K, V);

    const int smem_bytes = 4 * 2 * TILEH * 2;   // 73728
    static int attr_set = 0;
    cudaFuncSetAttribute(fa_hmma3_kernel,
                         cudaFuncAttributeMaxDynamicSharedMemorySize, smem_bytes);
    (void)attr_set;

    dim3 grid(QTILES, NBH);
    fa_hmma3_kernel<<<grid, NTH, smem_bytes>>>(O);
}